// round 15
// baseline (speedup 1.0000x reference)
#include <cuda_runtime.h>
#include <cuda_fp16.h>

// ---------------------------------------------------------------------------
// HSLSTMRegressor: 3-layer LSTM (B=128, T=256, IN=64, H=512) + head + MSE.
// Layer-pipelined persistent kernel: 3 groups x 32 CTAs, group g owns layer g.
// R15 = R14 (cp.async staging + fragment-pipelined mainloop, half-split chunk
// syncs, register epilogue) with the all-96-CTA step barrier replaced by
// PER-GROUP dependency barriers:
//   start of step s: wait (own group, s-1) and (group below, s-1)
//   before h-write : wait (group above, s-1)   [hidden behind the mainloop]
//   end of step s  : arrive on own group's split counters (16+16)
// Groups may skew by one step; jitter is absorbed, not propagated.
// NOTE: tcgen05 is NOT available (harness emits compute_100 PTX, no 'a').
// ---------------------------------------------------------------------------

#define Bn   128
#define Tn   256
#define INn  64
#define Hn   512
#define NCTA 96          // 3 groups x 32
#define NTHR 512
#define NSTEP (Tn + 2)   // 258 wavefront steps

// SMEM layout (bytes)
#define OFF_W 0          // 64 rows x 1032 halves (max) = 132096
#define OFF_A 132096     // 4 x 128 x 72 halves = 73728 (quad buffer)
#define SMEM_TOTAL 205824
#define ABUF_BYTES 18432

// ---------------- device scratch (static allocations only) -----------------
__device__ __align__(16) __half g_X[Tn * Bn * INn];      // x as [t][b][k], fp16
__device__ __align__(16) __half g_W0[2048 * 576];        // layer0 [Wih|Whh], gate-interleaved
__device__ __align__(16) __half g_W12[2 * 2048 * 1024];  // layers1,2 [Wih|Whh]
__device__ __align__(16) float  g_Bias[3 * 2048];        // b_ih + b_hh, gate-interleaved
__device__ __align__(16) __half g_Hbuf[3 * 2 * Bn * Hn]; // h per layer, ping-pong on t
// per-(step,group) split counters: index ((step*3 + g)*2 + j)*32, j in {0,1},
// each expects 16 arrivals (CTAs of the group split by cg&1).
__device__ unsigned int g_ctr[NSTEP * 3 * 2 * 32];

// ---------------------------------------------------------------------------
// launch 0: zero h state + barrier counters, build combined bias
__global__ void k_init_misc(const float* __restrict__ bih0, const float* __restrict__ bhh0,
                            const float* __restrict__ bihr, const float* __restrict__ bhhr) {
    int idx = blockIdx.x * blockDim.x + threadIdx.x;
    int stride = gridDim.x * blockDim.x;
    for (int i = idx; i < 3 * 2 * Bn * Hn; i += stride) g_Hbuf[i] = __float2half(0.f);
    for (int i = idx; i < NSTEP * 3 * 2 * 32; i += stride) g_ctr[i] = 0u;
    for (int i = idx; i < 3 * 2048; i += stride) {
        int l = i / 2048, r = i - l * 2048;
        int j = r >> 2, g = r & 3;
        int src = g * 512 + j;
        float v = (l == 0) ? (bih0[src] + bhh0[src])
                           : (bihr[(l - 1) * 2048 + src] + bhhr[(l - 1) * 2048 + src]);
        g_Bias[i] = v;
    }
}

// launch 1: x -> [t][b][k] fp16
__global__ void k_conv_x(const float* __restrict__ x) {
    int tot = Tn * Bn * INn;
    for (int i = blockIdx.x * blockDim.x + threadIdx.x; i < tot; i += gridDim.x * blockDim.x) {
        int t = i / (Bn * INn);
        int r = i - t * (Bn * INn);
        int b = r / INn;
        int k = r - b * INn;
        g_X[i] = __float2half(x[(size_t)b * Tn * INn + (size_t)t * INn + k]);
    }
}

// launch 2: all weights -> fp16, gate-interleaved rows (pr = 4*j + g)
__global__ void k_conv_w(const float* __restrict__ wih0, const float* __restrict__ whh0,
                         const float* __restrict__ wihr, const float* __restrict__ whhr) {
    const int W0TOT = 2048 * 576;
    const int tot = W0TOT + 2 * 2048 * 1024;
    for (int i = blockIdx.x * blockDim.x + threadIdx.x; i < tot; i += gridDim.x * blockDim.x) {
        if (i < W0TOT) {
            int r = i / 576, k = i - r * 576;
            int j = r >> 2, g = r & 3;
            int src = g * 512 + j;
            float v = (k < 64) ? wih0[src * 64 + k] : whh0[(size_t)src * 512 + (k - 64)];
            g_W0[i] = __float2half(v);
        } else {
            int rem = i - W0TOT;
            int l = rem >> 21;
            int rr = rem & ((1 << 21) - 1);
            int r = rr >> 10, k = rr & 1023;
            int j = r >> 2, g = r & 3;
            int src = g * 512 + j;
            float v = (k < 512) ? wihr[((size_t)l * 2048 + src) * 512 + k]
                                : whhr[((size_t)l * 2048 + src) * 512 + (k - 512)];
            g_W12[rem] = __float2half(v);
        }
    }
}

// ---------------------------------------------------------------------------
__device__ __forceinline__ void mma16816(float* c,
                                         unsigned a0, unsigned a1, unsigned a2, unsigned a3,
                                         unsigned b0, unsigned b1) {
    asm volatile(
        "mma.sync.aligned.m16n8k16.row.col.f32.f16.f16.f32 "
        "{%0,%1,%2,%3}, {%4,%5,%6,%7}, {%8,%9}, {%0,%1,%2,%3};\n"
        : "+f"(c[0]), "+f"(c[1]), "+f"(c[2]), "+f"(c[3])
        : "r"(a0), "r"(a1), "r"(a2), "r"(a3), "r"(b0), "r"(b1));
}

__device__ __forceinline__ void ldsm_x4(unsigned addr, unsigned& r0, unsigned& r1,
                                        unsigned& r2, unsigned& r3) {
    asm volatile("ldmatrix.sync.aligned.m8n8.x4.shared.b16 {%0,%1,%2,%3}, [%4];"
                 : "=r"(r0), "=r"(r1), "=r"(r2), "=r"(r3) : "r"(addr));
}

__device__ __forceinline__ void cp_async16(unsigned dst, const void* src) {
    asm volatile("cp.async.cg.shared.global [%0], [%1], 16;"
                 :: "r"(dst), "l"(__cvta_generic_to_global(src)) : "memory");
}

__device__ __forceinline__ void half_sync(int half) {
    asm volatile("bar.sync %0, %1;" :: "r"(half + 1), "r"(256) : "memory");
}

__device__ __forceinline__ void spin_ctr(const unsigned* p, unsigned target) {
    volatile unsigned* pc = (volatile unsigned*)p;
    long long spins = 0;
    while (*pc < target) {
        __nanosleep(20);
        if (++spins > (1LL << 28)) __trap();   // fail loud, never hang
    }
}

__device__ __forceinline__ float sigmoidf_(float x) { return 1.f / (1.f + __expf(-x)); }
__device__ __forceinline__ float tanh_fast(float x) {
    float r;
    asm("tanh.approx.f32 %0, %1;" : "=f"(r) : "f"(x));
    return r;
}

// launch 3 (== the ncu capture slot): the persistent LSTM kernel
__global__ void __launch_bounds__(NTHR, 1) k_lstm() {
    extern __shared__ __align__(16) unsigned char smraw[];
    __half* sW = (__half*)(smraw + OFF_W);
    __half* sA = (__half*)(smraw + OFF_A);

    const int tid  = threadIdx.x;
    const int grp  = blockIdx.x >> 5;       // layer this group owns (0..2)
    const int cg   = blockIdx.x & 31;       // col group: h-cols [cg*16, cg*16+16)
    const int lane = tid & 31;
    const int wid  = tid >> 5;
    const int half = wid >> 3;              // 0: rows 0-63, 1: rows 64-127
    const int w8   = wid & 7;               // warp index within half
    const int mrow0 = half * 64 + (w8 & 1) * 32;  // warp's 32 batch rows
    const int ng0   = (w8 >> 1) * 16;             // warp's 16 gate rows (of 64)
    const int lg    = lane >> 2;
    const int lt2   = (lane & 3) * 2;

    const int wcols = (grp == 0) ? 576 : 1024;
    const int wstr  = (grp == 0) ? 584 : 1032;
    const __half* gW = (grp == 0) ? g_W0
                      : g_W12 + (size_t)(grp - 1) * 2048 * 1024;

    // ---- load this CTA's 64 gate rows of its layer's weights into SMEM ----
    {
        int qpr = wcols >> 3;               // uint4 per row
        for (int i = tid; i < 64 * qpr; i += NTHR) {
            int r = i / qpr, q = i - r * qpr;
            *(uint4*)(sW + r * wstr + q * 8) =
                *(const uint4*)(gW + ((size_t)(cg * 64 + r)) * wcols + q * 8);
        }
    }

    // ---- per-thread biases for this thread's two 8-col fragments ----
    float bA[2][2];
#pragma unroll
    for (int ni = 0; ni < 2; ++ni) {
        int nc = ng0 + ni * 8 + lt2;
        bA[ni][0] = g_Bias[grp * 2048 + cg * 64 + nc];
        bA[ni][1] = g_Bias[grp * 2048 + cg * 64 + nc + 1];
    }
    float cst[4] = {0.f, 0.f, 0.f, 0.f};    // c-state in registers

    __syncthreads();

    const int arow = tid >> 2;              // A staging row: tid<256 -> 0-63 (half 0)
    const int acs  = (tid & 3) << 4;        // 16-half (32B) segment per thread

    // shared-space addresses
    const unsigned sA_s = (unsigned)__cvta_generic_to_shared(sA);
    const unsigned sW_s = (unsigned)__cvta_generic_to_shared(sW);
    const unsigned stg_off = (unsigned)(arow * 144 + acs * 2);  // bytes into a buffer
    const int a_r = ((lane >> 3) & 1) * 8 + (lane & 7);
    const int a_k = (lane >> 4) * 8;
    const unsigned a_off = (unsigned)(((mrow0 + a_r) * 72 + a_k) * 2);
    const int b_n = (lane & 7) + ((lane >> 4) & 1) * 8;
    const int b_k = ((lane >> 3) & 1) * 8;
    const unsigned b_off = (unsigned)(((ng0 + b_n) * wstr + b_k) * 2);

    // epilogue coordinates (fixed per thread)
    const int e_row = (lane & 1) * 8 + lg;            // + mrow0 + mi*16
    const int e_j   = (ng0 >> 2) + ((lane & 3) >> 1); // + ni*2

    for (int step = 0; step < NSTEP; ++step) {
        const int t = step - grp;
        if (t >= 0 && t < Tn) {
            // ---- dependency wait: (own group, s-1) and (group below, s-1) ----
            if (step > 0) {
                int sb = (step - 1) * 6;              // (step-1)*3*2
                if (tid < 2)              spin_ctr(&g_ctr[(sb + grp * 2 + tid) * 32], 16u);
                else if (tid < 4 && grp > 0)
                                          spin_ctr(&g_ctr[(sb + (grp - 1) * 2 + (tid - 2)) * 32], 16u);
                if (tid < 4) __threadfence();         // acquire before reading peer h
            }
            __syncthreads();

            const __half* srcA;
            int strideA, nA;
            if (grp == 0) { srcA = g_X + (size_t)t * Bn * INn; strideA = INn; nA = 1; }
            else          { srcA = g_Hbuf + ((size_t)((grp - 1) * 2 + (t & 1))) * Bn * Hn;
                            strideA = Hn; nA = 8; }
            const __half* srcB = g_Hbuf + ((size_t)(grp * 2 + ((t & 1) ^ 1))) * Bn * Hn;
            const int nch = nA + 8;

            float acc[2][2][4];
#pragma unroll
            for (int mi = 0; mi < 2; ++mi)
#pragma unroll
                for (int ni = 0; ni < 2; ++ni)
#pragma unroll
                    for (int q = 0; q < 4; ++q) acc[mi][ni][q] = 0.f;

            // prologue: async-stage chunks 0..2 (one commit group per chunk)
#pragma unroll
            for (int pc = 0; pc < 3; ++pc) {
                const __half* p = (pc < nA)
                    ? srcA + (size_t)arow * strideA + (pc << 6) + acs
                    : srcB + (size_t)arow * Hn + ((pc - nA) << 6) + acs;
                unsigned dst = sA_s + (unsigned)(pc * ABUF_BYTES) + stg_off;
                cp_async16(dst, p);
                cp_async16(dst + 16, p + 8);
                asm volatile("cp.async.commit_group;" ::: "memory");
            }

            for (int ch = 0; ch < nch; ++ch) {
                const int b4 = ch & 3;
                if (ch + 2 < nch) asm volatile("cp.async.wait_group 2;" ::: "memory");
                else              asm volatile("cp.async.wait_group 0;" ::: "memory");
                half_sync(half);            // only this half's 256 threads

                if (ch + 3 < nch) {
                    int c = ch + 3;
                    const __half* p = (c < nA)
                        ? srcA + (size_t)arow * strideA + (c << 6) + acs
                        : srcB + (size_t)arow * Hn + ((c - nA) << 6) + acs;
                    unsigned dst = sA_s + (unsigned)((c & 3) * ABUF_BYTES) + stg_off;
                    cp_async16(dst, p);
                    cp_async16(dst + 16, p + 8);
                    asm volatile("cp.async.commit_group;" ::: "memory");
                }

                const unsigned abase = sA_s + (unsigned)(b4 * ABUF_BYTES) + a_off;
                const unsigned bbase = sW_s + b_off + (unsigned)((ch << 6) * 2);

                // fragment double-buffered k-loop: LDSM(kk+16) before MMA(kk)
                unsigned a0[2][4], a1[2][4], bb[2][4];
                ldsm_x4(abase,            a0[0][0], a0[0][1], a0[0][2], a0[0][3]);
                ldsm_x4(abase + 16 * 144, a1[0][0], a1[0][1], a1[0][2], a1[0][3]);
                ldsm_x4(bbase,            bb[0][0], bb[0][1], bb[0][2], bb[0][3]);
#pragma unroll
                for (int kk = 0; kk < 64; kk += 16) {
                    const int cur = (kk >> 4) & 1;
                    const int nxt = cur ^ 1;
                    if (kk < 48) {
                        ldsm_x4(abase + (kk + 16) * 2,
                                a0[nxt][0], a0[nxt][1], a0[nxt][2], a0[nxt][3]);
                        ldsm_x4(abase + 16 * 144 + (kk + 16) * 2,
                                a1[nxt][0], a1[nxt][1], a1[nxt][2], a1[nxt][3]);
                        ldsm_x4(bbase + (kk + 16) * 2,
                                bb[nxt][0], bb[nxt][1], bb[nxt][2], bb[nxt][3]);
                    }
                    mma16816(acc[0][0], a0[cur][0], a0[cur][1], a0[cur][2], a0[cur][3],
                             bb[cur][0], bb[cur][1]);
                    mma16816(acc[1][0], a1[cur][0], a1[cur][1], a1[cur][2], a1[cur][3],
                             bb[cur][0], bb[cur][1]);
                    mma16816(acc[0][1], a0[cur][0], a0[cur][1], a0[cur][2], a0[cur][3],
                             bb[cur][2], bb[cur][3]);
                    mma16816(acc[1][1], a1[cur][0], a1[cur][1], a1[cur][2], a1[cur][3],
                             bb[cur][2], bb[cur][3]);
                }
            }

            // ---- write-gate: group above must have finished step-1 (it read the
            // parity buffer we are about to overwrite). Hidden behind mainloop.
            if (grp < 2 && step > 0) {
                const unsigned* c0 = &g_ctr[((step - 1) * 6 + (grp + 1) * 2) * 32];
                spin_ctr(c0, 16u);
                spin_ctr(c0 + 32, 16u);
                __threadfence();
            }

            // ---- register epilogue: shuffle-exchange gates within lane pairs ----
            __half* hdst = g_Hbuf + ((size_t)(grp * 2 + (t & 1))) * Bn * Hn;
#pragma unroll
            for (int mi = 0; mi < 2; ++mi)
#pragma unroll
                for (int ni = 0; ni < 2; ++ni) {
                    float g0 = acc[mi][ni][0] + bA[ni][0];
                    float g1 = acc[mi][ni][1] + bA[ni][1];
                    float g2 = acc[mi][ni][2] + bA[ni][0];
                    float g3 = acc[mi][ni][3] + bA[ni][1];
                    float s0 = __shfl_xor_sync(0xFFFFFFFFu, g0, 1);
                    float s1 = __shfl_xor_sync(0xFFFFFFFFu, g1, 1);
                    float s2 = __shfl_xor_sync(0xFFFFFFFFu, g2, 1);
                    float s3 = __shfl_xor_sync(0xFFFFFFFFu, g3, 1);
                    float gi, gf, gg, go;
                    if ((lane & 1) == 0) { gi = g0; gf = g1; gg = s0; go = s1; }
                    else                 { gi = s2; gf = s3; gg = g2; go = g3; }
                    int ci = mi * 2 + ni;
                    float cn = sigmoidf_(gf) * cst[ci] + sigmoidf_(gi) * tanh_fast(gg);
                    float hn = sigmoidf_(go) * tanh_fast(cn);
                    cst[ci] = cn;
                    int row = mrow0 + mi * 16 + e_row;
                    int col = cg * 16 + e_j + ni * 2;
                    hdst[(size_t)row * Hn + col] = __float2half(hn);
                }
        }

        // ---- arrive on own group's split counter (unconditional every step) ----
        __threadfence();                    // release h-writes
        __syncthreads();                    // all threads of CTA done
        if (tid == 0)
            atomicAdd(&g_ctr[(step * 6 + grp * 2 + (cg & 1)) * 32], 1u);
    }
}

// ---------------------------------------------------------------------------
// launch 4: output head + MSE loss
__global__ void k_out(const float* __restrict__ wout, const float* __restrict__ bout,
                      const float* __restrict__ y, float* __restrict__ out, int out_size) {
    __shared__ float sred[128];
    int b = threadIdx.x;
    const __half* h = g_Hbuf + ((size_t)(2 * 2 + ((Tn - 1) & 1))) * Bn * Hn + (size_t)b * Hn;
    float s = 0.f;
    for (int j = 0; j < Hn; ++j) s += __half2float(h[j]) * wout[j];
    s += bout[0];
    float d = s - y[b];
    sred[b] = d * d;
    __syncthreads();
    for (int st = 64; st > 0; st >>= 1) {
        if (b < st) sred[b] += sred[b + st];
        __syncthreads();
    }
    float loss = sred[0] * (1.f / 128.f);
    if (out_size == 1) {
        if (b == 0) out[0] = loss;
    } else {
        if (b < out_size) out[b] = s;
        if (b == 0 && out_size > Bn) out[Bn] = loss;
    }
}

// ---------------------------------------------------------------------------
extern "C" void kernel_launch(void* const* d_in, const int* in_sizes, int n_in,
                              void* d_out, int out_size) {
    const float* x    = (const float*)d_in[0];
    const float* y    = (const float*)d_in[1];
    const float* wih0 = (const float*)d_in[2];
    const float* whh0 = (const float*)d_in[3];
    const float* bih0 = (const float*)d_in[4];
    const float* bhh0 = (const float*)d_in[5];
    const float* wihr = (const float*)d_in[6];
    const float* whhr = (const float*)d_in[7];
    const float* bihr = (const float*)d_in[8];
    const float* bhhr = (const float*)d_in[9];
    const float* wout = (const float*)d_in[10];
    const float* bout = (const float*)d_in[11];

    cudaFuncSetAttribute(k_lstm, cudaFuncAttributeMaxDynamicSharedMemorySize, SMEM_TOTAL);

    k_init_misc<<<512, 256>>>(bih0, bhh0, bihr, bhhr);   // launch 0
    k_conv_x<<<512, 256>>>(x);                            // launch 1
    k_conv_w<<<1536, 256>>>(wih0, whh0, wihr, whhr);      // launch 2
    k_lstm<<<NCTA, NTHR, SMEM_TOTAL>>>();                 // launch 3  (ncu slot)
    k_out<<<1, 128>>>(wout, bout, y, (float*)d_out, out_size);  // launch 4
}

// round 16
// speedup vs baseline: 1.1093x; 1.1093x over previous
#include <cuda_runtime.h>
#include <cuda_fp16.h>

// ---------------------------------------------------------------------------
// HSLSTMRegressor: 3-layer LSTM (B=128, T=256, IN=64, H=512) + head + MSE.
// Layer-pipelined persistent kernel: 3 groups x 32 CTAs, group g owns layer g.
// 258 wavefront steps, one fused global barrier per step (8-way split ctrs).
// R16 = R14 (cp.async staging + fragment-pipelined mainloop, register
// epilogue; the R15 per-group barrier REGRESSED and is reverted) with the
// per-chunk staging sync domain split again: 4 independent 128-thread
// quarters (quarter q owns batch rows 32q..32q+32, warps 4q..4q+3).
// NOTE: tcgen05 is NOT available (harness emits compute_100 PTX, no 'a').
// ---------------------------------------------------------------------------

#define Bn   128
#define Tn   256
#define INn  64
#define Hn   512
#define NCTA 96          // 3 groups x 32
#define NTHR 512
#define NSTEP (Tn + 2)   // 258 wavefront steps

// SMEM layout (bytes)
#define OFF_W 0          // 64 rows x 1032 halves (max) = 132096
#define OFF_A 132096     // 4 x 128 x 72 halves = 73728 (quad buffer)
#define SMEM_TOTAL 205824
#define ABUF_BYTES 18432

// ---------------- device scratch (static allocations only) -----------------
__device__ __align__(16) __half g_X[Tn * Bn * INn];      // x as [t][b][k], fp16
__device__ __align__(16) __half g_W0[2048 * 576];        // layer0 [Wih|Whh], gate-interleaved
__device__ __align__(16) __half g_W12[2 * 2048 * 1024];  // layers1,2 [Wih|Whh]
__device__ __align__(16) float  g_Bias[3 * 2048];        // b_ih + b_hh, gate-interleaved
__device__ __align__(16) __half g_Hbuf[3 * 2 * Bn * Hn]; // h per layer, ping-pong on t
__device__ unsigned int g_ctr[NSTEP * 256];              // 8 counters/step, 128B apart

// ---------------------------------------------------------------------------
// launch 0: zero h state + barrier counters, build combined bias
__global__ void k_init_misc(const float* __restrict__ bih0, const float* __restrict__ bhh0,
                            const float* __restrict__ bihr, const float* __restrict__ bhhr) {
    int idx = blockIdx.x * blockDim.x + threadIdx.x;
    int stride = gridDim.x * blockDim.x;
    for (int i = idx; i < 3 * 2 * Bn * Hn; i += stride) g_Hbuf[i] = __float2half(0.f);
    for (int i = idx; i < NSTEP * 256; i += stride) g_ctr[i] = 0u;
    for (int i = idx; i < 3 * 2048; i += stride) {
        int l = i / 2048, r = i - l * 2048;
        int j = r >> 2, g = r & 3;
        int src = g * 512 + j;
        float v = (l == 0) ? (bih0[src] + bhh0[src])
                           : (bihr[(l - 1) * 2048 + src] + bhhr[(l - 1) * 2048 + src]);
        g_Bias[i] = v;
    }
}

// launch 1: x -> [t][b][k] fp16
__global__ void k_conv_x(const float* __restrict__ x) {
    int tot = Tn * Bn * INn;
    for (int i = blockIdx.x * blockDim.x + threadIdx.x; i < tot; i += gridDim.x * blockDim.x) {
        int t = i / (Bn * INn);
        int r = i - t * (Bn * INn);
        int b = r / INn;
        int k = r - b * INn;
        g_X[i] = __float2half(x[(size_t)b * Tn * INn + (size_t)t * INn + k]);
    }
}

// launch 2: all weights -> fp16, gate-interleaved rows (pr = 4*j + g)
__global__ void k_conv_w(const float* __restrict__ wih0, const float* __restrict__ whh0,
                         const float* __restrict__ wihr, const float* __restrict__ whhr) {
    const int W0TOT = 2048 * 576;
    const int tot = W0TOT + 2 * 2048 * 1024;
    for (int i = blockIdx.x * blockDim.x + threadIdx.x; i < tot; i += gridDim.x * blockDim.x) {
        if (i < W0TOT) {
            int r = i / 576, k = i - r * 576;
            int j = r >> 2, g = r & 3;
            int src = g * 512 + j;
            float v = (k < 64) ? wih0[src * 64 + k] : whh0[(size_t)src * 512 + (k - 64)];
            g_W0[i] = __float2half(v);
        } else {
            int rem = i - W0TOT;
            int l = rem >> 21;
            int rr = rem & ((1 << 21) - 1);
            int r = rr >> 10, k = rr & 1023;
            int j = r >> 2, g = r & 3;
            int src = g * 512 + j;
            float v = (k < 512) ? wihr[((size_t)l * 2048 + src) * 512 + k]
                                : whhr[((size_t)l * 2048 + src) * 512 + (k - 512)];
            g_W12[rem] = __float2half(v);
        }
    }
}

// ---------------------------------------------------------------------------
__device__ __forceinline__ void mma16816(float* c,
                                         unsigned a0, unsigned a1, unsigned a2, unsigned a3,
                                         unsigned b0, unsigned b1) {
    asm volatile(
        "mma.sync.aligned.m16n8k16.row.col.f32.f16.f16.f32 "
        "{%0,%1,%2,%3}, {%4,%5,%6,%7}, {%8,%9}, {%0,%1,%2,%3};\n"
        : "+f"(c[0]), "+f"(c[1]), "+f"(c[2]), "+f"(c[3])
        : "r"(a0), "r"(a1), "r"(a2), "r"(a3), "r"(b0), "r"(b1));
}

__device__ __forceinline__ void ldsm_x4(unsigned addr, unsigned& r0, unsigned& r1,
                                        unsigned& r2, unsigned& r3) {
    asm volatile("ldmatrix.sync.aligned.m8n8.x4.shared.b16 {%0,%1,%2,%3}, [%4];"
                 : "=r"(r0), "=r"(r1), "=r"(r2), "=r"(r3) : "r"(addr));
}

__device__ __forceinline__ void cp_async16(unsigned dst, const void* src) {
    asm volatile("cp.async.cg.shared.global [%0], [%1], 16;"
                 :: "r"(dst), "l"(__cvta_generic_to_global(src)) : "memory");
}

__device__ __forceinline__ void qtr_sync(int q) {
    asm volatile("bar.sync %0, %1;" :: "r"(q + 1), "r"(128) : "memory");
}

__device__ __forceinline__ float sigmoidf_(float x) { return 1.f / (1.f + __expf(-x)); }
__device__ __forceinline__ float tanh_fast(float x) {
    float r;
    asm("tanh.approx.f32 %0, %1;" : "=f"(r) : "f"(x));
    return r;
}

// launch 3 (== the ncu capture slot): the persistent LSTM kernel
__global__ void __launch_bounds__(NTHR, 1) k_lstm() {
    extern __shared__ __align__(16) unsigned char smraw[];
    __half* sW = (__half*)(smraw + OFF_W);
    __half* sA = (__half*)(smraw + OFF_A);

    const int tid  = threadIdx.x;
    const int grp  = blockIdx.x >> 5;       // layer this group owns (0..2)
    const int cg   = blockIdx.x & 31;       // col group: h-cols [cg*16, cg*16+16)
    const int lane = tid & 31;
    const int wid  = tid >> 5;
    const int qtr  = wid >> 2;              // quarter q: batch rows 32q..32q+32
    const int w4   = wid & 3;               // warp index within quarter
    const int mrow0 = qtr * 32;             // warp's 32 batch rows
    const int ng0   = w4 * 16;              // warp's 16 gate rows (of 64)
    const int lg    = lane >> 2;
    const int lt2   = (lane & 3) * 2;

    const int wcols = (grp == 0) ? 576 : 1024;
    const int wstr  = (grp == 0) ? 584 : 1032;
    const __half* gW = (grp == 0) ? g_W0
                      : g_W12 + (size_t)(grp - 1) * 2048 * 1024;

    // ---- load this CTA's 64 gate rows of its layer's weights into SMEM ----
    {
        int qpr = wcols >> 3;               // uint4 per row
        for (int i = tid; i < 64 * qpr; i += NTHR) {
            int r = i / qpr, q = i - r * qpr;
            *(uint4*)(sW + r * wstr + q * 8) =
                *(const uint4*)(gW + ((size_t)(cg * 64 + r)) * wcols + q * 8);
        }
    }

    // ---- per-thread biases for this thread's two 8-col fragments ----
    float bA[2][2];
#pragma unroll
    for (int ni = 0; ni < 2; ++ni) {
        int nc = ng0 + ni * 8 + lt2;
        bA[ni][0] = g_Bias[grp * 2048 + cg * 64 + nc];
        bA[ni][1] = g_Bias[grp * 2048 + cg * 64 + nc + 1];
    }
    float cst[4] = {0.f, 0.f, 0.f, 0.f};    // c-state in registers

    __syncthreads();

    const int arow = tid >> 2;              // staging row (within owning quarter)
    const int acs  = (tid & 3) << 4;        // 16-half (32B) segment per thread

    // shared-space addresses
    const unsigned sA_s = (unsigned)__cvta_generic_to_shared(sA);
    const unsigned sW_s = (unsigned)__cvta_generic_to_shared(sW);
    const unsigned stg_off = (unsigned)(arow * 144 + acs * 2);  // bytes into a buffer
    const int a_r = ((lane >> 3) & 1) * 8 + (lane & 7);
    const int a_k = (lane >> 4) * 8;
    const unsigned a_off = (unsigned)(((mrow0 + a_r) * 72 + a_k) * 2);
    const int b_n = (lane & 7) + ((lane >> 4) & 1) * 8;
    const int b_k = ((lane >> 3) & 1) * 8;
    const unsigned b_off = (unsigned)(((ng0 + b_n) * wstr + b_k) * 2);

    // epilogue coordinates (fixed per thread)
    const int e_row = (lane & 1) * 8 + lg;            // + mrow0 + mi*16
    const int e_j   = (ng0 >> 2) + ((lane & 3) >> 1); // + ni*2

    for (int step = 0; step < NSTEP; ++step) {
        const int t = step - grp;
        if (t >= 0 && t < Tn) {
            const __half* srcA;
            int strideA, nA;
            if (grp == 0) { srcA = g_X + (size_t)t * Bn * INn; strideA = INn; nA = 1; }
            else          { srcA = g_Hbuf + ((size_t)((grp - 1) * 2 + (t & 1))) * Bn * Hn;
                            strideA = Hn; nA = 8; }
            const __half* srcB = g_Hbuf + ((size_t)(grp * 2 + ((t & 1) ^ 1))) * Bn * Hn;
            const int nch = nA + 8;

            float acc[2][2][4];
#pragma unroll
            for (int mi = 0; mi < 2; ++mi)
#pragma unroll
                for (int ni = 0; ni < 2; ++ni)
#pragma unroll
                    for (int q = 0; q < 4; ++q) acc[mi][ni][q] = 0.f;

            // prologue: async-stage chunks 0..2 (one commit group per chunk)
#pragma unroll
            for (int pc = 0; pc < 3; ++pc) {
                const __half* p = (pc < nA)
                    ? srcA + (size_t)arow * strideA + (pc << 6) + acs
                    : srcB + (size_t)arow * Hn + ((pc - nA) << 6) + acs;
                unsigned dst = sA_s + (unsigned)(pc * ABUF_BYTES) + stg_off;
                cp_async16(dst, p);
                cp_async16(dst + 16, p + 8);
                asm volatile("cp.async.commit_group;" ::: "memory");
            }

            for (int ch = 0; ch < nch; ++ch) {
                const int b4 = ch & 3;
                // chunk ch's group complete (exact tail handling)
                if (ch + 2 < nch) asm volatile("cp.async.wait_group 2;" ::: "memory");
                else              asm volatile("cp.async.wait_group 0;" ::: "memory");
                qtr_sync(qtr);              // only this quarter's 128 threads

                // async-prefetch chunk ch+3: its buffer held chunk ch-1, whose
                // MMAs every thread of this quarter finished before this sync.
                if (ch + 3 < nch) {
                    int c = ch + 3;
                    const __half* p = (c < nA)
                        ? srcA + (size_t)arow * strideA + (c << 6) + acs
                        : srcB + (size_t)arow * Hn + ((c - nA) << 6) + acs;
                    unsigned dst = sA_s + (unsigned)((c & 3) * ABUF_BYTES) + stg_off;
                    cp_async16(dst, p);
                    cp_async16(dst + 16, p + 8);
                    asm volatile("cp.async.commit_group;" ::: "memory");
                }

                const unsigned abase = sA_s + (unsigned)(b4 * ABUF_BYTES) + a_off;
                const unsigned bbase = sW_s + b_off + (unsigned)((ch << 6) * 2);

                // fragment double-buffered k-loop: LDSM(kk+16) before MMA(kk)
                unsigned a0[2][4], a1[2][4], bb[2][4];
                ldsm_x4(abase,            a0[0][0], a0[0][1], a0[0][2], a0[0][3]);
                ldsm_x4(abase + 16 * 144, a1[0][0], a1[0][1], a1[0][2], a1[0][3]);
                ldsm_x4(bbase,            bb[0][0], bb[0][1], bb[0][2], bb[0][3]);
#pragma unroll
                for (int kk = 0; kk < 64; kk += 16) {
                    const int cur = (kk >> 4) & 1;
                    const int nxt = cur ^ 1;
                    if (kk < 48) {
                        ldsm_x4(abase + (kk + 16) * 2,
                                a0[nxt][0], a0[nxt][1], a0[nxt][2], a0[nxt][3]);
                        ldsm_x4(abase + 16 * 144 + (kk + 16) * 2,
                                a1[nxt][0], a1[nxt][1], a1[nxt][2], a1[nxt][3]);
                        ldsm_x4(bbase + (kk + 16) * 2,
                                bb[nxt][0], bb[nxt][1], bb[nxt][2], bb[nxt][3]);
                    }
                    mma16816(acc[0][0], a0[cur][0], a0[cur][1], a0[cur][2], a0[cur][3],
                             bb[cur][0], bb[cur][1]);
                    mma16816(acc[1][0], a1[cur][0], a1[cur][1], a1[cur][2], a1[cur][3],
                             bb[cur][0], bb[cur][1]);
                    mma16816(acc[0][1], a0[cur][0], a0[cur][1], a0[cur][2], a0[cur][3],
                             bb[cur][2], bb[cur][3]);
                    mma16816(acc[1][1], a1[cur][0], a1[cur][1], a1[cur][2], a1[cur][3],
                             bb[cur][2], bb[cur][3]);
                }
            }

            // ---- register epilogue: shuffle-exchange gates within lane pairs ----
            __half* hdst = g_Hbuf + ((size_t)(grp * 2 + (t & 1))) * Bn * Hn;
#pragma unroll
            for (int mi = 0; mi < 2; ++mi)
#pragma unroll
                for (int ni = 0; ni < 2; ++ni) {
                    float g0 = acc[mi][ni][0] + bA[ni][0];
                    float g1 = acc[mi][ni][1] + bA[ni][1];
                    float g2 = acc[mi][ni][2] + bA[ni][0];
                    float g3 = acc[mi][ni][3] + bA[ni][1];
                    float s0 = __shfl_xor_sync(0xFFFFFFFFu, g0, 1);
                    float s1 = __shfl_xor_sync(0xFFFFFFFFu, g1, 1);
                    float s2 = __shfl_xor_sync(0xFFFFFFFFu, g2, 1);
                    float s3 = __shfl_xor_sync(0xFFFFFFFFu, g3, 1);
                    float gi, gf, gg, go;
                    if ((lane & 1) == 0) { gi = g0; gf = g1; gg = s0; go = s1; }
                    else                 { gi = s2; gf = s3; gg = g2; go = g3; }
                    int ci = mi * 2 + ni;
                    float cn = sigmoidf_(gf) * cst[ci] + sigmoidf_(gi) * tanh_fast(gg);
                    float hn = sigmoidf_(go) * tanh_fast(cn);
                    cst[ci] = cn;
                    int row = mrow0 + mi * 16 + e_row;
                    int col = cg * 16 + e_j + ni * 2;
                    hdst[(size_t)row * Hn + col] = __float2half(hn);
                }
        }

        // ---- global wavefront barrier: 8-way split counters ----
        __threadfence();                    // release h-writes (all threads)
        __syncthreads();                    // rejoin all quarters
        if (tid == 0)
            atomicAdd(&g_ctr[step * 256 + (blockIdx.x & 7) * 32], 1u);
        if (tid < 8) {
            volatile unsigned* pc = &g_ctr[step * 256 + tid * 32];
            long long spins = 0;
            while (*pc < (unsigned)(NCTA / 8)) {
                __nanosleep(20);
                if (++spins > (1LL << 28)) __trap();   // fail loud, never hang
            }
            __threadfence();                // acquire before reading peer h
        }
        __syncthreads();
    }
}

// ---------------------------------------------------------------------------
// launch 4: output head + MSE loss
__global__ void k_out(const float* __restrict__ wout, const float* __restrict__ bout,
                      const float* __restrict__ y, float* __restrict__ out, int out_size) {
    __shared__ float sred[128];
    int b = threadIdx.x;
    const __half* h = g_Hbuf + ((size_t)(2 * 2 + ((Tn - 1) & 1))) * Bn * Hn + (size_t)b * Hn;
    float s = 0.f;
    for (int j = 0; j < Hn; ++j) s += __half2float(h[j]) * wout[j];
    s += bout[0];
    float d = s - y[b];
    sred[b] = d * d;
    __syncthreads();
    for (int st = 64; st > 0; st >>= 1) {
        if (b < st) sred[b] += sred[b + st];
        __syncthreads();
    }
    float loss = sred[0] * (1.f / 128.f);
    if (out_size == 1) {
        if (b == 0) out[0] = loss;
    } else {
        if (b < out_size) out[b] = s;
        if (b == 0 && out_size > Bn) out[Bn] = loss;
    }
}

// ---------------------------------------------------------------------------
extern "C" void kernel_launch(void* const* d_in, const int* in_sizes, int n_in,
                              void* d_out, int out_size) {
    const float* x    = (const float*)d_in[0];
    const float* y    = (const float*)d_in[1];
    const float* wih0 = (const float*)d_in[2];
    const float* whh0 = (const float*)d_in[3];
    const float* bih0 = (const float*)d_in[4];
    const float* bhh0 = (const float*)d_in[5];
    const float* wihr = (const float*)d_in[6];
    const float* whhr = (const float*)d_in[7];
    const float* bihr = (const float*)d_in[8];
    const float* bhhr = (const float*)d_in[9];
    const float* wout = (const float*)d_in[10];
    const float* bout = (const float*)d_in[11];

    cudaFuncSetAttribute(k_lstm, cudaFuncAttributeMaxDynamicSharedMemorySize, SMEM_TOTAL);

    k_init_misc<<<512, 256>>>(bih0, bhh0, bihr, bhhr);   // launch 0
    k_conv_x<<<512, 256>>>(x);                            // launch 1
    k_conv_w<<<1536, 256>>>(wih0, whh0, wihr, whhr);      // launch 2
    k_lstm<<<NCTA, NTHR, SMEM_TOTAL>>>();                 // launch 3  (ncu slot)
    k_out<<<1, 128>>>(wout, bout, y, (float*)d_out, out_size);  // launch 4
}